// round 14
// baseline (speedup 1.0000x reference)
#include <cuda_runtime.h>

// DAGConstraintLayer: out = tree_min_project(sigmoid(x)) over (262144, 127) fp32.
// parent(i)=(i-1)/2, complete binary tree depth 7.
//
// sigmoid monotone => min(sig(a),sig(b)) = sig(min(a,b)): propagate min on raw x
// (FMNMX only), sigmoid applied once per element at store time.
//
// R14 = R12 code byte-for-byte (2-stage cp.async.cg ring, 32-row tiles, tanh
// sigmoid) with ONLY the launch grid changed: 148*6 = 888.
// Critical: __launch_bounds__(256, 7) is RETAINED - it is what pins regs=32
// (R13 showed min-blocks=6 relaxes ptxas to 40 regs, confounding the grid
// test). min-blocks is a compiler register constraint, independent of the
// launched grid. This isolates the queued-CTA straggler-tail variable:
// 32.5KB smem + reserve -> 6 CTAs/SM resident, so grid 1036 queues 148 CTAs
// behind wave 1; grid 888 makes every CTA resident from t=0.

#define NODES 127
#define ROWS_PER_TILE 32
#define THREADS 256
#define TILE_FLOATS (ROWS_PER_TILE * NODES)   // 4064
#define TILE_F4 (TILE_FLOATS / 4)             // 1016
#define TILE_BYTES (TILE_FLOATS * 4)          // 16256 (128B-aligned tiles)
#define SMEM_BYTES (2 * TILE_BYTES)           // 32512

__device__ __forceinline__ void cp_async16(void* smem_dst, const void* gmem_src) {
    unsigned s = (unsigned)__cvta_generic_to_shared(smem_dst);
    asm volatile("cp.async.cg.shared.global [%0], [%1], 16;\n" :: "r"(s), "l"(gmem_src));
}
__device__ __forceinline__ void cp_commit() {
    asm volatile("cp.async.commit_group;\n" ::: "memory");
}
template <int N>
__device__ __forceinline__ void cp_wait() {
    asm volatile("cp.async.wait_group %0;\n" :: "n"(N) : "memory");
}

__device__ __forceinline__ float fast_sigmoid(float v) {
    // sigmoid(v) = 0.5*tanh(0.5v) + 0.5 : FMUL + MUFU.TANH + FFMA (1 MUFU)
    float t;
    asm("tanh.approx.f32 %0, %1;" : "=f"(t) : "f"(0.5f * v));
    return fmaf(0.5f, t, 0.5f);
}

// Register-chain DFS: path-min rides in a register (no LDS-after-STS dependence).
template <int I, int REM>
__device__ __forceinline__ void dfs_min(float* __restrict__ r, float pmin) {
    float v = fminf(r[I], pmin);
    r[I] = v;
    if constexpr (REM > 0) {
        dfs_min<2 * I + 1, REM - 1>(r, v);
        dfs_min<2 * I + 2, REM - 1>(r, v);
    }
}

extern __shared__ float smem[];  // 2 tiles

__global__ void __launch_bounds__(THREADS, 7)   // pins regs=32 (do not relax)
dag_constraint_kernel(const float* __restrict__ x, float* __restrict__ out,
                      int ntiles) {
    const int tid = threadIdx.x;
    float* buf0 = smem;
    float* buf1 = smem + TILE_FLOATS;

    const int t0 = blockIdx.x;

    // Prologue: prefetch first tile into buf0.
    if (t0 < ntiles) {
        const float4* __restrict__ src = (const float4*)(x + (size_t)t0 * TILE_FLOATS);
        float4* dst = (float4*)buf0;
        #pragma unroll
        for (int j = tid; j < TILE_F4; j += THREADS) cp_async16(dst + j, src + j);
    }
    cp_commit();

    int stage = 0;
    for (int t = t0; t < ntiles; t += gridDim.x) {
        // Prefetch next tile into the other buffer (fully consumed last iter;
        // end-of-iteration barrier guarantees it).
        const int nxt = t + gridDim.x;
        float* cur = stage ? buf1 : buf0;
        float* oth = stage ? buf0 : buf1;
        if (nxt < ntiles) {
            const float4* __restrict__ src = (const float4*)(x + (size_t)nxt * TILE_FLOATS);
            float4* dst = (float4*)oth;
            #pragma unroll
            for (int j = tid; j < TILE_F4; j += THREADS) cp_async16(dst + j, src + j);
        }
        cp_commit();
        cp_wait<1>();        // tile t complete (groups retire in order)
        __syncthreads();     // make cp.async data visible across threads

        // ---- P2: raw min-propagation; one warp per level-3 subtree ----
        {
            const int sub = tid >> 5;        // warp id 0..7 (uniform per warp)
            const int lane = tid & 31;       // row within tile
            float* r = cur + lane * NODES;   // odd stride -> bank-conflict-free

            const float v0 = r[0];                   // node 0: read-only
            const int a1 = 1 + (sub >> 2);           // node 1 or 2
            const float v1 = fminf(r[a1], v0);
            if ((sub & 3) == 0) r[a1] = v1;          // idempotent-race writes
            const int a2 = 3 + (sub >> 1);           // nodes 3..6
            const float v2 = fminf(r[a2], v1);
            if ((sub & 1) == 0) r[a2] = v2;
            switch (sub) {                           // warp-uniform
                case 0: dfs_min<7,  3>(r, v2); break;   // 15 nodes each,
                case 1: dfs_min<8,  3>(r, v2); break;   // levels 3..6
                case 2: dfs_min<9,  3>(r, v2); break;
                case 3: dfs_min<10, 3>(r, v2); break;
                case 4: dfs_min<11, 3>(r, v2); break;
                case 5: dfs_min<12, 3>(r, v2); break;
                case 6: dfs_min<13, 3>(r, v2); break;
                case 7: dfs_min<14, 3>(r, v2); break;
            }
        }
        __syncthreads();

        // ---- P3: sigmoid (tanh-based) + coalesced streaming store ----
        {
            const float4* s4 = (const float4*)cur;
            float4* __restrict__ gout = (float4*)(out + (size_t)t * TILE_FLOATS);
            #pragma unroll
            for (int j = tid; j < TILE_F4; j += THREADS) {
                float4 v = s4[j];
                v.x = fast_sigmoid(v.x);
                v.y = fast_sigmoid(v.y);
                v.z = fast_sigmoid(v.z);
                v.w = fast_sigmoid(v.w);
                __stcs(gout + j, v);
            }
        }
        __syncthreads();     // all reads of 'cur' done before it's refilled
        stage ^= 1;
    }
}

extern "C" void kernel_launch(void* const* d_in, const int* in_sizes, int n_in,
                              void* d_out, int out_size) {
    const float* x = (const float*)d_in[0];
    float* out = (float*)d_out;

    const int total = in_sizes[0];              // 262144 * 127
    const int rows = total / NODES;             // 262144
    const int ntiles = rows / ROWS_PER_TILE;    // 8192

    int grid = 148 * 6;                         // all CTAs resident from t=0
    if (grid > ntiles) grid = ntiles;

    dag_constraint_kernel<<<grid, THREADS, SMEM_BYTES>>>(x, out, ntiles);
}

// round 15
// speedup vs baseline: 1.0670x; 1.0670x over previous
#include <cuda_runtime.h>

// DAGConstraintLayer: out = tree_min_project(sigmoid(x)) over (262144, 127) fp32.
// parent(i)=(i-1)/2, complete binary tree depth 7.
//
// sigmoid monotone => min(sig(a),sig(b)) = sig(min(a,b)): propagate min on raw x
// (FMNMX only), sigmoid applied once per element at store time.
//
// FINAL (= R12, the measured optimum across 14 rounds of ablation):
//   - 2-stage cp.async.cg ring, 32-row tiles (16256 B), block-cooperative
//     aligned float4 prefetch; __launch_bounds__(256,7) pins regs=32.
//   - grid 148*7 = 1036: the extra 148 CTAs backfill SMs as first-wave CTAs
//     drain (R14 proved grid 888 is 1.6us slower at equal regs).
//   - P2: one warp per level-3 subtree, register-chain DFS, value-idempotent
//     ancestor writes (no LDS-after-STS dependence on the critical path).
//   - P3: sigmoid(v) = 0.5*tanh(0.5v)+0.5 (single MUFU.TANH) + __stcs stores.
// Measured: 37.4us kernel, 70.8% DRAM, 7.1 TB/s combined r+w stream (89% of
// 8 TB/s spec), issue 29% (compute fully hidden) - the mixed read/write DRAM
// turnaround ceiling for this access pattern. Ablations ruled out: barrier
// count (0-3), pipeline depth (1-3), occupancy (34-87%), register/shuffle
// compute, L2 cache hints, and alternate grids (888/1184).

#define NODES 127
#define ROWS_PER_TILE 32
#define THREADS 256
#define TILE_FLOATS (ROWS_PER_TILE * NODES)   // 4064
#define TILE_F4 (TILE_FLOATS / 4)             // 1016
#define TILE_BYTES (TILE_FLOATS * 4)          // 16256 (128B-aligned tiles)
#define SMEM_BYTES (2 * TILE_BYTES)           // 32512

__device__ __forceinline__ void cp_async16(void* smem_dst, const void* gmem_src) {
    unsigned s = (unsigned)__cvta_generic_to_shared(smem_dst);
    asm volatile("cp.async.cg.shared.global [%0], [%1], 16;\n" :: "r"(s), "l"(gmem_src));
}
__device__ __forceinline__ void cp_commit() {
    asm volatile("cp.async.commit_group;\n" ::: "memory");
}
template <int N>
__device__ __forceinline__ void cp_wait() {
    asm volatile("cp.async.wait_group %0;\n" :: "n"(N) : "memory");
}

__device__ __forceinline__ float fast_sigmoid(float v) {
    // sigmoid(v) = 0.5*tanh(0.5v) + 0.5 : FMUL + MUFU.TANH + FFMA (1 MUFU)
    float t;
    asm("tanh.approx.f32 %0, %1;" : "=f"(t) : "f"(0.5f * v));
    return fmaf(0.5f, t, 0.5f);
}

// Register-chain DFS: path-min rides in a register (no LDS-after-STS dependence).
template <int I, int REM>
__device__ __forceinline__ void dfs_min(float* __restrict__ r, float pmin) {
    float v = fminf(r[I], pmin);
    r[I] = v;
    if constexpr (REM > 0) {
        dfs_min<2 * I + 1, REM - 1>(r, v);
        dfs_min<2 * I + 2, REM - 1>(r, v);
    }
}

extern __shared__ float smem[];  // 2 tiles

__global__ void __launch_bounds__(THREADS, 7)   // pins regs=32 (do not relax)
dag_constraint_kernel(const float* __restrict__ x, float* __restrict__ out,
                      int ntiles) {
    const int tid = threadIdx.x;
    float* buf0 = smem;
    float* buf1 = smem + TILE_FLOATS;

    const int t0 = blockIdx.x;

    // Prologue: prefetch first tile into buf0.
    if (t0 < ntiles) {
        const float4* __restrict__ src = (const float4*)(x + (size_t)t0 * TILE_FLOATS);
        float4* dst = (float4*)buf0;
        #pragma unroll
        for (int j = tid; j < TILE_F4; j += THREADS) cp_async16(dst + j, src + j);
    }
    cp_commit();

    int stage = 0;
    for (int t = t0; t < ntiles; t += gridDim.x) {
        // Prefetch next tile into the other buffer (fully consumed last iter;
        // end-of-iteration barrier guarantees it).
        const int nxt = t + gridDim.x;
        float* cur = stage ? buf1 : buf0;
        float* oth = stage ? buf0 : buf1;
        if (nxt < ntiles) {
            const float4* __restrict__ src = (const float4*)(x + (size_t)nxt * TILE_FLOATS);
            float4* dst = (float4*)oth;
            #pragma unroll
            for (int j = tid; j < TILE_F4; j += THREADS) cp_async16(dst + j, src + j);
        }
        cp_commit();
        cp_wait<1>();        // tile t complete (groups retire in order)
        __syncthreads();     // make cp.async data visible across threads

        // ---- P2: raw min-propagation; one warp per level-3 subtree ----
        {
            const int sub = tid >> 5;        // warp id 0..7 (uniform per warp)
            const int lane = tid & 31;       // row within tile
            float* r = cur + lane * NODES;   // odd stride -> bank-conflict-free

            const float v0 = r[0];                   // node 0: read-only
            const int a1 = 1 + (sub >> 2);           // node 1 or 2
            const float v1 = fminf(r[a1], v0);
            if ((sub & 3) == 0) r[a1] = v1;          // idempotent-race writes
            const int a2 = 3 + (sub >> 1);           // nodes 3..6
            const float v2 = fminf(r[a2], v1);
            if ((sub & 1) == 0) r[a2] = v2;
            switch (sub) {                           // warp-uniform
                case 0: dfs_min<7,  3>(r, v2); break;   // 15 nodes each,
                case 1: dfs_min<8,  3>(r, v2); break;   // levels 3..6
                case 2: dfs_min<9,  3>(r, v2); break;
                case 3: dfs_min<10, 3>(r, v2); break;
                case 4: dfs_min<11, 3>(r, v2); break;
                case 5: dfs_min<12, 3>(r, v2); break;
                case 6: dfs_min<13, 3>(r, v2); break;
                case 7: dfs_min<14, 3>(r, v2); break;
            }
        }
        __syncthreads();

        // ---- P3: sigmoid (tanh-based) + coalesced streaming store ----
        {
            const float4* s4 = (const float4*)cur;
            float4* __restrict__ gout = (float4*)(out + (size_t)t * TILE_FLOATS);
            #pragma unroll
            for (int j = tid; j < TILE_F4; j += THREADS) {
                float4 v = s4[j];
                v.x = fast_sigmoid(v.x);
                v.y = fast_sigmoid(v.y);
                v.z = fast_sigmoid(v.z);
                v.w = fast_sigmoid(v.w);
                __stcs(gout + j, v);
            }
        }
        __syncthreads();     // all reads of 'cur' done before it's refilled
        stage ^= 1;
    }
}

extern "C" void kernel_launch(void* const* d_in, const int* in_sizes, int n_in,
                              void* d_out, int out_size) {
    const float* x = (const float*)d_in[0];
    float* out = (float*)d_out;

    const int total = in_sizes[0];              // 262144 * 127
    const int rows = total / NODES;             // 262144
    const int ntiles = rows / ROWS_PER_TILE;    // 8192

    int grid = 148 * 7;                         // 1036: backfill wave proven best
    if (grid > ntiles) grid = ntiles;

    dag_constraint_kernel<<<grid, THREADS, SMEM_BYTES>>>(x, out, ntiles);
}

// round 16
// speedup vs baseline: 1.0963x; 1.0274x over previous
#include <cuda_runtime.h>

// DAGConstraintLayer: out = tree_min_project(sigmoid(x)) over (262144, 127) fp32.
// parent(i)=(i-1)/2, complete binary tree depth 7.
//
// sigmoid monotone => min(sig(a),sig(b)) = sig(min(a,b)): propagate min on raw x
// (FMNMX only), sigmoid applied once per element at store time.
//
// FINAL (= R12 optimum; R15 control re-bench of the identical binary measured
// +/-2us kernel noise, confirming convergence):
//   - 2-stage cp.async.cg ring, 32-row tiles (16256 B), block-cooperative
//     aligned float4 prefetch; __launch_bounds__(256,7) pins regs=32.
//   - P2: one warp per level-3 subtree, register-chain DFS, value-idempotent
//     ancestor writes (no LDS-after-STS dependence on the critical path).
//   - P3: sigmoid(v) = 0.5*tanh(0.5v)+0.5 (single MUFU.TANH) + __stcs stores.
// Measured best: 37.4us kernel, 70.8% DRAM, ~7.1 TB/s combined r+w stream
// (89% of 8 TB/s spec), issue 29% (compute fully hidden) - the mixed
// read/write DRAM turnaround ceiling. 15 rounds of ablation ruled out:
// architecture (4 families), tile size (16-128 rows), pipeline depth (1-3),
// barrier count (0-3), occupancy (34-87%), sigmoid variant, L2 cache hints,
// grid size (888/1036/1184), and TMA-bulk (LTS cap is path-independent).

#define NODES 127
#define ROWS_PER_TILE 32
#define THREADS 256
#define TILE_FLOATS (ROWS_PER_TILE * NODES)   // 4064
#define TILE_F4 (TILE_FLOATS / 4)             // 1016
#define TILE_BYTES (TILE_FLOATS * 4)          // 16256 (128B-aligned tiles)
#define SMEM_BYTES (2 * TILE_BYTES)           // 32512

__device__ __forceinline__ void cp_async16(void* smem_dst, const void* gmem_src) {
    unsigned s = (unsigned)__cvta_generic_to_shared(smem_dst);
    asm volatile("cp.async.cg.shared.global [%0], [%1], 16;\n" :: "r"(s), "l"(gmem_src));
}
__device__ __forceinline__ void cp_commit() {
    asm volatile("cp.async.commit_group;\n" ::: "memory");
}
template <int N>
__device__ __forceinline__ void cp_wait() {
    asm volatile("cp.async.wait_group %0;\n" :: "n"(N) : "memory");
}

__device__ __forceinline__ float fast_sigmoid(float v) {
    // sigmoid(v) = 0.5*tanh(0.5v) + 0.5 : FMUL + MUFU.TANH + FFMA (1 MUFU)
    float t;
    asm("tanh.approx.f32 %0, %1;" : "=f"(t) : "f"(0.5f * v));
    return fmaf(0.5f, t, 0.5f);
}

// Register-chain DFS: path-min rides in a register (no LDS-after-STS dependence).
template <int I, int REM>
__device__ __forceinline__ void dfs_min(float* __restrict__ r, float pmin) {
    float v = fminf(r[I], pmin);
    r[I] = v;
    if constexpr (REM > 0) {
        dfs_min<2 * I + 1, REM - 1>(r, v);
        dfs_min<2 * I + 2, REM - 1>(r, v);
    }
}

extern __shared__ float smem[];  // 2 tiles

__global__ void __launch_bounds__(THREADS, 7)   // pins regs=32 (do not relax)
dag_constraint_kernel(const float* __restrict__ x, float* __restrict__ out,
                      int ntiles) {
    const int tid = threadIdx.x;
    float* buf0 = smem;
    float* buf1 = smem + TILE_FLOATS;

    const int t0 = blockIdx.x;

    // Prologue: prefetch first tile into buf0.
    if (t0 < ntiles) {
        const float4* __restrict__ src = (const float4*)(x + (size_t)t0 * TILE_FLOATS);
        float4* dst = (float4*)buf0;
        #pragma unroll
        for (int j = tid; j < TILE_F4; j += THREADS) cp_async16(dst + j, src + j);
    }
    cp_commit();

    int stage = 0;
    for (int t = t0; t < ntiles; t += gridDim.x) {
        // Prefetch next tile into the other buffer (fully consumed last iter;
        // end-of-iteration barrier guarantees it).
        const int nxt = t + gridDim.x;
        float* cur = stage ? buf1 : buf0;
        float* oth = stage ? buf0 : buf1;
        if (nxt < ntiles) {
            const float4* __restrict__ src = (const float4*)(x + (size_t)nxt * TILE_FLOATS);
            float4* dst = (float4*)oth;
            #pragma unroll
            for (int j = tid; j < TILE_F4; j += THREADS) cp_async16(dst + j, src + j);
        }
        cp_commit();
        cp_wait<1>();        // tile t complete (groups retire in order)
        __syncthreads();     // make cp.async data visible across threads

        // ---- P2: raw min-propagation; one warp per level-3 subtree ----
        {
            const int sub = tid >> 5;        // warp id 0..7 (uniform per warp)
            const int lane = tid & 31;       // row within tile
            float* r = cur + lane * NODES;   // odd stride -> bank-conflict-free

            const float v0 = r[0];                   // node 0: read-only
            const int a1 = 1 + (sub >> 2);           // node 1 or 2
            const float v1 = fminf(r[a1], v0);
            if ((sub & 3) == 0) r[a1] = v1;          // idempotent-race writes
            const int a2 = 3 + (sub >> 1);           // nodes 3..6
            const float v2 = fminf(r[a2], v1);
            if ((sub & 1) == 0) r[a2] = v2;
            switch (sub) {                           // warp-uniform
                case 0: dfs_min<7,  3>(r, v2); break;   // 15 nodes each,
                case 1: dfs_min<8,  3>(r, v2); break;   // levels 3..6
                case 2: dfs_min<9,  3>(r, v2); break;
                case 3: dfs_min<10, 3>(r, v2); break;
                case 4: dfs_min<11, 3>(r, v2); break;
                case 5: dfs_min<12, 3>(r, v2); break;
                case 6: dfs_min<13, 3>(r, v2); break;
                case 7: dfs_min<14, 3>(r, v2); break;
            }
        }
        __syncthreads();

        // ---- P3: sigmoid (tanh-based) + coalesced streaming store ----
        {
            const float4* s4 = (const float4*)cur;
            float4* __restrict__ gout = (float4*)(out + (size_t)t * TILE_FLOATS);
            #pragma unroll
            for (int j = tid; j < TILE_F4; j += THREADS) {
                float4 v = s4[j];
                v.x = fast_sigmoid(v.x);
                v.y = fast_sigmoid(v.y);
                v.z = fast_sigmoid(v.z);
                v.w = fast_sigmoid(v.w);
                __stcs(gout + j, v);
            }
        }
        __syncthreads();     // all reads of 'cur' done before it's refilled
        stage ^= 1;
    }
}

extern "C" void kernel_launch(void* const* d_in, const int* in_sizes, int n_in,
                              void* d_out, int out_size) {
    const float* x = (const float*)d_in[0];
    float* out = (float*)d_out;

    const int total = in_sizes[0];              // 262144 * 127
    const int rows = total / NODES;             // 262144
    const int ntiles = rows / ROWS_PER_TILE;    // 8192

    int grid = 148 * 7;                         // 1036 (888/1184 within noise)
    if (grid > ntiles) grid = ntiles;

    dag_constraint_kernel<<<grid, THREADS, SMEM_BYTES>>>(x, out, ntiles);
}